// round 2
// baseline (speedup 1.0000x reference)
#include <cuda_runtime.h>
#include <math.h>

#define BB   4
#define NPTS 16384
#define MPTS 4096
#define C1   128
#define C2   256
#define HCH  256
#define K1   384
#define NTOT (BB*NPTS)   // 65536

// ---------------- scratch (device globals: no allocation allowed) ----------------
__device__ float4 g_kpack[BB*MPTS];                         // 256 KB
__device__ float  g_kfT[(size_t)BB*MPTS*C2];                // 16.8 MB  known_feats point-major
__device__ float  g_featsT[(size_t)BB*NPTS*K1];             // 100.7 MB concat feats, point-major
__device__ int    g_idx3[NTOT*3];
__device__ float  g_w3[NTOT*3];
__device__ float  g_y1[(size_t)NTOT*HCH];                   // 67.1 MB  GEMM1 raw out, point-major
__device__ float  g_sum1[HCH], g_sq1[HCH], g_scale1[HCH], g_shift1[HCH];
__device__ float  g_sum2[HCH], g_sq2[HCH], g_scale2[HCH], g_shift2[HCH];

// ---------------- kernels ----------------

__global__ void zero_stats_kernel() {
    int t = threadIdx.x;
    g_sum1[t] = 0.f; g_sq1[t] = 0.f;
    g_sum2[t] = 0.f; g_sq2[t] = 0.f;
}

__global__ void prep_known_kernel(const float* __restrict__ known) {
    int t = blockIdx.x * 256 + threadIdx.x;
    if (t >= BB * MPTS) return;
    float x = known[t*3+0], y = known[t*3+1], z = known[t*3+2];
    g_kpack[t] = make_float4(x, y, z, x*x + y*y + z*z);
}

// known_feats [b][c][p] (256 x 4096) -> g_kfT [b][p][c]
__global__ void transpose_kf_kernel(const float* __restrict__ kf) {
    __shared__ float tile[32][33];
    int b = blockIdx.z;
    int p0 = blockIdx.x * 32, c0 = blockIdx.y * 32;
    const float* src = kf + (size_t)b * C2 * MPTS;
    float* dst = g_kfT + (size_t)b * MPTS * C2;
#pragma unroll
    for (int r = 0; r < 32; r += 8)
        tile[threadIdx.y + r][threadIdx.x] =
            src[(size_t)(c0 + threadIdx.y + r) * MPTS + p0 + threadIdx.x];
    __syncthreads();
#pragma unroll
    for (int r = 0; r < 32; r += 8)
        dst[(size_t)(p0 + threadIdx.y + r) * C2 + c0 + threadIdx.x] =
            tile[threadIdx.x][threadIdx.y + r];
}

// unknown_feats [b][c][i] (128 x 16384) -> g_featsT[b][i][256 + c]
__global__ void transpose_uf_kernel(const float* __restrict__ uf) {
    __shared__ float tile[32][33];
    int b = blockIdx.z;
    int i0 = blockIdx.x * 32, c0 = blockIdx.y * 32;
    const float* src = uf + (size_t)b * C1 * NPTS;
    float* dst = g_featsT + (size_t)b * NPTS * K1;
#pragma unroll
    for (int r = 0; r < 32; r += 8)
        tile[threadIdx.y + r][threadIdx.x] =
            src[(size_t)(c0 + threadIdx.y + r) * NPTS + i0 + threadIdx.x];
    __syncthreads();
#pragma unroll
    for (int r = 0; r < 32; r += 8)
        dst[(size_t)(i0 + threadIdx.y + r) * K1 + C2 + c0 + threadIdx.x] =
            tile[threadIdx.x][threadIdx.y + r];
}

// exhaustive 3-NN: one thread per unknown point; knowns staged in smem (4 tiles of 1024)
__global__ void __launch_bounds__(128) three_nn_kernel(const float* __restrict__ unknown) {
    int g = blockIdx.x * 128 + threadIdx.x;          // 0..65535
    int b = g >> 14;
    float ux = unknown[g*3+0], uy = unknown[g*3+1], uz = unknown[g*3+2];
    float ca = -2.f * ux, cb = -2.f * uy, cc = -2.f * uz;
    float u2 = ux*ux + uy*uy + uz*uz;
    float s0 = 3.4e38f, s1 = 3.4e38f, s2 = 3.4e38f;
    int   i0 = 0, i1 = 0, i2 = 0;

    __shared__ float4 sk[1024];
    const float4* kp = g_kpack + b * MPTS;

    for (int t = 0; t < 4; t++) {
        __syncthreads();
        for (int q = threadIdx.x; q < 1024; q += 128) sk[q] = kp[t*1024 + q];
        __syncthreads();
#pragma unroll 4
        for (int jj = 0; jj < 1024; jj++) {
            float4 k4 = sk[jj];
            float s = fmaf(k4.x, ca, fmaf(k4.y, cb, fmaf(k4.z, cc, k4.w)));
            if (s < s2) {
                int j = t*1024 + jj;
                if (s < s1) {
                    s2 = s1; i2 = i1;
                    if (s < s0) { s1 = s0; i1 = i0; s0 = s; i0 = j; }
                    else        { s1 = s;  i1 = j; }
                } else { s2 = s; i2 = j; }
            }
        }
    }
    float d0 = s0 + u2, d1 = s1 + u2, d2 = s2 + u2;
    float r0 = 1.f / (d0 + 1e-8f), r1 = 1.f / (d1 + 1e-8f), r2 = 1.f / (d2 + 1e-8f);
    float rs = r0 + r1 + r2;
    g_idx3[g*3+0] = i0; g_idx3[g*3+1] = i1; g_idx3[g*3+2] = i2;
    g_w3[g*3+0] = r0 / rs; g_w3[g*3+1] = r1 / rs; g_w3[g*3+2] = r2 / rs;
}

// gather + weighted sum -> g_featsT[b][i][0..255]; one warp per point
__global__ void interp_kernel() {
    int warp = threadIdx.x >> 5, lane = threadIdx.x & 31;
    int g = blockIdx.x * 8 + warp;                   // 0..65535
    int b = g >> 14;
    int p0 = g_idx3[g*3+0], p1 = g_idx3[g*3+1], p2 = g_idx3[g*3+2];
    float w0 = g_w3[g*3+0], w1 = g_w3[g*3+1], w2 = g_w3[g*3+2];
    const float4* f0 = (const float4*)&g_kfT[((size_t)(b*MPTS + p0)) * C2];
    const float4* f1 = (const float4*)&g_kfT[((size_t)(b*MPTS + p1)) * C2];
    const float4* f2 = (const float4*)&g_kfT[((size_t)(b*MPTS + p2)) * C2];
    float4* dst = (float4*)&g_featsT[(size_t)g * K1];
#pragma unroll
    for (int h = 0; h < 2; h++) {
        int v = lane*2 + h;
        float4 a = f0[v], c = f1[v], d = f2[v];
        float4 r;
        r.x = fmaf(w0, a.x, fmaf(w1, c.x, w2 * d.x));
        r.y = fmaf(w0, a.y, fmaf(w1, c.y, w2 * d.y));
        r.z = fmaf(w0, a.z, fmaf(w1, c.z, w2 * d.z));
        r.w = fmaf(w0, a.w, fmaf(w1, c.w, w2 * d.w));
        dst[v] = r;
    }
}

// GEMM1: y1[j][o] = sum_c W1[o][c] * featsT[j][c]   (K=384)
__global__ void __launch_bounds__(256) gemm1_kernel(const float* __restrict__ W1) {
    __shared__ float sW[16][128];
    __shared__ float sF[16][128];
    int j0 = blockIdx.x * 128;
    int o0 = blockIdx.y * 128;
    int tid = threadIdx.x;
    int to = tid & 15, tj = tid >> 4;
    int lr = tid >> 2;            // 0..63
    int lc = (tid & 3) * 4;       // 0,4,8,12
    float acc[8][8];
#pragma unroll
    for (int r = 0; r < 8; r++)
#pragma unroll
        for (int c = 0; c < 8; c++) acc[r][c] = 0.f;

    for (int kc = 0; kc < K1; kc += 16) {
#pragma unroll
        for (int h = 0; h < 2; h++) {
            int row = lr + h*64;
            float4 v = *(const float4*)&W1[(size_t)(o0 + row) * K1 + kc + lc];
            sW[lc+0][row] = v.x; sW[lc+1][row] = v.y; sW[lc+2][row] = v.z; sW[lc+3][row] = v.w;
            float4 f = *(const float4*)&g_featsT[(size_t)(j0 + row) * K1 + kc + lc];
            sF[lc+0][row] = f.x; sF[lc+1][row] = f.y; sF[lc+2][row] = f.z; sF[lc+3][row] = f.w;
        }
        __syncthreads();
#pragma unroll
        for (int k = 0; k < 16; k++) {
            float a[8], bv[8];
            ((float4*)a)[0]  = *(const float4*)&sW[k][to*8];
            ((float4*)a)[1]  = *(const float4*)&sW[k][to*8+4];
            ((float4*)bv)[0] = *(const float4*)&sF[k][tj*8];
            ((float4*)bv)[1] = *(const float4*)&sF[k][tj*8+4];
#pragma unroll
            for (int r = 0; r < 8; r++)
#pragma unroll
                for (int c = 0; c < 8; c++)
                    acc[r][c] = fmaf(bv[r], a[c], acc[r][c]);
        }
        __syncthreads();
    }
#pragma unroll
    for (int r = 0; r < 8; r++) {
        float* dst = &g_y1[(size_t)(j0 + tj*8 + r) * HCH + o0 + to*8];
        *(float4*)dst       = make_float4(acc[r][0], acc[r][1], acc[r][2], acc[r][3]);
        *(float4*)(dst + 4) = make_float4(acc[r][4], acc[r][5], acc[r][6], acc[r][7]);
    }
}

// per-channel sums over y1 (point-major)
__global__ void stats1_kernel() {
    int o = threadIdx.x;
    size_t j0 = (size_t)blockIdx.x * 256;
    const float* p = g_y1 + j0 * HCH + o;
    float s = 0.f, q = 0.f;
    for (int r = 0; r < 256; r++) {
        float v = p[(size_t)r * HCH];
        s += v; q = fmaf(v, v, q);
    }
    atomicAdd(&g_sum1[o], s);
    atomicAdd(&g_sq1[o], q);
}

// which==1 -> BN1 params, which==2 -> BN2 params. Globals referenced from
// device code only (host-side references to __device__ symbols are invalid).
__global__ void finalize_kernel(const float* __restrict__ gamma,
                                const float* __restrict__ beta,
                                int which) {
    int o = threadIdx.x;
    const float invN = 1.f / (float)NTOT;
    float s  = (which == 1) ? g_sum1[o] : g_sum2[o];
    float q  = (which == 1) ? g_sq1[o]  : g_sq2[o];
    float mu  = s * invN;
    float var = q * invN - mu * mu;
    float sc  = gamma[o] * rsqrtf(var + 1e-5f);
    float sh  = fmaf(-mu, sc, beta[o]);
    if (which == 1) { g_scale1[o] = sc; g_shift1[o] = sh; }
    else            { g_scale2[o] = sc; g_shift2[o] = sh; }
}

// GEMM2: out_raw[b][o][i] = sum_c W2[o][c] * relu(bn1(y1[j][c]))   (K=256), channel-major out
__global__ void __launch_bounds__(256) gemm2_kernel(const float* __restrict__ W2,
                                                    float* __restrict__ out) {
    __shared__ float sW[16][128];
    __shared__ float sF[16][128];
    int j0 = blockIdx.x * 128;
    int o0 = blockIdx.y * 128;
    int tid = threadIdx.x;
    int to = tid & 15, tj = tid >> 4;
    int lr = tid >> 2;
    int lc = (tid & 3) * 4;
    float acc[8][8];
#pragma unroll
    for (int r = 0; r < 8; r++)
#pragma unroll
        for (int c = 0; c < 8; c++) acc[r][c] = 0.f;

    for (int kc = 0; kc < HCH; kc += 16) {
        int cbase = kc + lc;
        float sc0 = g_scale1[cbase+0], sh0 = g_shift1[cbase+0];
        float sc1 = g_scale1[cbase+1], sh1 = g_shift1[cbase+1];
        float sc2 = g_scale1[cbase+2], sh2 = g_shift1[cbase+2];
        float sc3 = g_scale1[cbase+3], sh3 = g_shift1[cbase+3];
#pragma unroll
        for (int h = 0; h < 2; h++) {
            int row = lr + h*64;
            float4 v = *(const float4*)&W2[(size_t)(o0 + row) * HCH + kc + lc];
            sW[lc+0][row] = v.x; sW[lc+1][row] = v.y; sW[lc+2][row] = v.z; sW[lc+3][row] = v.w;
            float4 f = *(const float4*)&g_y1[(size_t)(j0 + row) * HCH + cbase];
            sF[lc+0][row] = fmaxf(0.f, fmaf(f.x, sc0, sh0));
            sF[lc+1][row] = fmaxf(0.f, fmaf(f.y, sc1, sh1));
            sF[lc+2][row] = fmaxf(0.f, fmaf(f.z, sc2, sh2));
            sF[lc+3][row] = fmaxf(0.f, fmaf(f.w, sc3, sh3));
        }
        __syncthreads();
#pragma unroll
        for (int k = 0; k < 16; k++) {
            float a[8], bv[8];
            ((float4*)a)[0]  = *(const float4*)&sW[k][to*8];
            ((float4*)a)[1]  = *(const float4*)&sW[k][to*8+4];
            ((float4*)bv)[0] = *(const float4*)&sF[k][tj*8];
            ((float4*)bv)[1] = *(const float4*)&sF[k][tj*8+4];
#pragma unroll
            for (int r = 0; r < 8; r++)
#pragma unroll
                for (int c = 0; c < 8; c++)
                    acc[r][c] = fmaf(bv[r], a[c], acc[r][c]);
        }
        __syncthreads();
    }
    // transposed epilogue: out[(b*256 + o) * 16384 + i], raw (BN2 applied later)
    int j = j0 + tj*8;               // 8 consecutive j owned by this thread
    int b = j >> 14;
    int i = j & (NPTS - 1);
#pragma unroll
    for (int c = 0; c < 8; c++) {
        int o = o0 + to*8 + c;
        float* dst = out + ((size_t)(b * HCH + o)) * NPTS + i;
        *(float4*)dst       = make_float4(acc[0][c], acc[1][c], acc[2][c], acc[3][c]);
        *(float4*)(dst + 4) = make_float4(acc[4][c], acc[5][c], acc[6][c], acc[7][c]);
    }
}

// per-channel sums over channel-major raw output
__global__ void stats2_kernel(const float* __restrict__ y2) {
    int row = blockIdx.x;            // b*256 + o
    int o = row & 255;
    const float* p = y2 + (size_t)row * NPTS;
    float s = 0.f, q = 0.f;
    for (int i = threadIdx.x; i < NPTS; i += 256) {
        float v = p[i];
        s += v; q = fmaf(v, v, q);
    }
    __shared__ float ss[256], sq[256];
    ss[threadIdx.x] = s; sq[threadIdx.x] = q;
    __syncthreads();
    for (int w = 128; w > 0; w >>= 1) {
        if (threadIdx.x < w) { ss[threadIdx.x] += ss[threadIdx.x+w]; sq[threadIdx.x] += sq[threadIdx.x+w]; }
        __syncthreads();
    }
    if (threadIdx.x == 0) {
        atomicAdd(&g_sum2[o], ss[0]);
        atomicAdd(&g_sq2[o], sq[0]);
    }
}

// in-place BN2 + ReLU on channel-major output
__global__ void bnrelu_out_kernel(float* __restrict__ out) {
    size_t t = (size_t)blockIdx.x * 256 + threadIdx.x;   // float4 index
    int o = (int)((t >> 12) & 255);                      // 4096 float4 per row
    float sc = g_scale2[o], sh = g_shift2[o];
    float4 v = ((float4*)out)[t];
    v.x = fmaxf(0.f, fmaf(v.x, sc, sh));
    v.y = fmaxf(0.f, fmaf(v.y, sc, sh));
    v.z = fmaxf(0.f, fmaf(v.z, sc, sh));
    v.w = fmaxf(0.f, fmaf(v.w, sc, sh));
    ((float4*)out)[t] = v;
}

// ---------------- launch ----------------
extern "C" void kernel_launch(void* const* d_in, const int* in_sizes, int n_in,
                              void* d_out, int out_size) {
    const float* unknown       = (const float*)d_in[0];
    const float* known         = (const float*)d_in[1];
    const float* unknown_feats = (const float*)d_in[2];
    const float* known_feats   = (const float*)d_in[3];
    const float* W1            = (const float*)d_in[4];
    const float* gamma1        = (const float*)d_in[5];
    const float* beta1         = (const float*)d_in[6];
    const float* W2            = (const float*)d_in[7];
    const float* gamma2        = (const float*)d_in[8];
    const float* beta2         = (const float*)d_in[9];
    float* out = (float*)d_out;

    zero_stats_kernel<<<1, 256>>>();
    prep_known_kernel<<<(BB*MPTS + 255)/256, 256>>>(known);
    transpose_kf_kernel<<<dim3(MPTS/32, C2/32, BB), dim3(32, 8)>>>(known_feats);
    transpose_uf_kernel<<<dim3(NPTS/32, C1/32, BB), dim3(32, 8)>>>(unknown_feats);
    three_nn_kernel<<<NTOT/128, 128>>>(unknown);
    interp_kernel<<<NTOT/8, 256>>>();
    gemm1_kernel<<<dim3(NTOT/128, HCH/128), 256>>>(W1);
    stats1_kernel<<<NTOT/256, 256>>>();
    finalize_kernel<<<1, 256>>>(gamma1, beta1, 1);
    gemm2_kernel<<<dim3(NTOT/128, HCH/128), 256>>>(W2, out);
    stats2_kernel<<<BB*HCH, 256>>>(out);
    finalize_kernel<<<1, 256>>>(gamma2, beta2, 2);
    bnrelu_out_kernel<<<(BB*HCH*(NPTS/4))/256, 256>>>(out);
}